// round 15
// baseline (speedup 1.0000x reference)
#include <cuda_runtime.h>
#include <math.h>

#define B_   2
#define N_   6
#define C_   80
#define FH_  16
#define FW_  44
#define D_   112
#define NX_  128
#define NY_  128
#define BN_  (B_*N_)
#define PIX_ (FH_*FW_)          // 704
#define NPIX_ (BN_*PIX_)        // 8448
#define CELLS_ (NX_*NY_)        // 16384
#define NQ_  (C_/4)             // 20 channel quads
#define OUTN_ (B_*C_*CELLS_)    // 2621440
#define CAP_  512               // smem hash capacity (cells per column-CTA)

__device__ float g_comb[BN_][16];    // bda @ s2e @ inv(intrin)
__device__ float g_idainv[BN_][16];  // inv(ida)
// quad-planar accumulator: float4 plane per (b, q): [B][NQ][CELLS][4]
__device__ __align__(128) float g_scratch[OUTN_];

// ---------------------------------------------------------------------------
// parallel prep: one block, 384 threads (entry-parallel adjugate inverses)
// ---------------------------------------------------------------------------
__global__ __launch_bounds__(384) void prep_kernel(const float* __restrict__ s2e,
                                                   const float* __restrict__ intrin,
                                                   const float* __restrict__ ida,
                                                   const float* __restrict__ bda) {
    __shared__ double adj[2][BN_][16];
    __shared__ double rdet[2][BN_];
    __shared__ double Tm[BN_][16];
    int t = threadIdx.x;

    if (t < 2 * BN_ * 16) {
        int pair = t / (BN_ * 16);
        int rem  = t - pair * (BN_ * 16);
        int i    = rem >> 4;
        int k    = rem & 15;
        const float* src = (pair ? ida : intrin) + i * 16;
        double m[16];
        #pragma unroll
        for (int j = 0; j < 16; j++) m[j] = (double)src[j];
        int r = k >> 2, c = k & 3;
        int rr[3], cc[3], nr = 0, nc = 0;
        #pragma unroll
        for (int j = 0; j < 4; j++) { if (j != c) rr[nr++] = j; }
        #pragma unroll
        for (int j = 0; j < 4; j++) { if (j != r) cc[nc++] = j; }
        double a = m[rr[0]*4+cc[0]], bb = m[rr[0]*4+cc[1]], cx = m[rr[0]*4+cc[2]];
        double d = m[rr[1]*4+cc[0]], e  = m[rr[1]*4+cc[1]], f  = m[rr[1]*4+cc[2]];
        double g = m[rr[2]*4+cc[0]], h  = m[rr[2]*4+cc[1]], ii = m[rr[2]*4+cc[2]];
        double det3 = a*(e*ii - f*h) - bb*(d*ii - f*g) + cx*(d*h - e*g);
        adj[pair][i][k] = (((r + c) & 1) ? -det3 : det3);
    }
    __syncthreads();

    if (t < 2 * BN_) {
        int pair = t / BN_;
        int i    = t - pair * BN_;
        const float* src = (pair ? ida : intrin) + i * 16;
        double det = 0.0;
        #pragma unroll
        for (int j = 0; j < 4; j++) det += (double)src[j] * adj[pair][i][j*4];
        rdet[pair][i] = 1.0 / det;
    }
    __syncthreads();

    if (t < 2 * BN_ * 16) {
        int pair = t / (BN_ * 16);
        int rem  = t - pair * (BN_ * 16);
        adj[pair][rem >> 4][rem & 15] *= rdet[pair][rem >> 4];
    }
    __syncthreads();

    if (t < BN_ * 16) {
        int i = t >> 4, k = t & 15;
        int r = k >> 2, c = k & 3;
        double s = 0.0;
        #pragma unroll
        for (int j = 0; j < 4; j++) s += (double)s2e[i*16 + r*4 + j] * adj[0][i][j*4 + c];
        Tm[i][k] = s;
    }
    __syncthreads();

    if (t < BN_ * 16) {
        int i = t >> 4, k = t & 15;
        int r = k >> 2, c = k & 3;
        int b = i / N_;
        double s = 0.0;
        #pragma unroll
        for (int j = 0; j < 4; j++) s += (double)bda[b*16 + r*4 + j] * Tm[i][j*4 + c];
        g_comb[i][k]   = (float)s;
        g_idainv[i][k] = (float)adj[1][i][k];
    }
}

__global__ __launch_bounds__(256) void zero_scratch_kernel() {
    int i = blockIdx.x * blockDim.x + threadIdx.x;
    float4* p = (float4*)g_scratch + i * 4;
    #pragma unroll
    for (int j = 0; j < 4; j++) p[j] = make_float4(0.f, 0.f, 0.f, 0.f);
}

// ---------------------------------------------------------------------------
// column-fused main: one CTA (256 thr, 8 warps) per (bn, w) image column.
//   Lane owns 4 CONSECUTIVE depth bins -> in-register run pre-merge before
//   smem hash accumulate; then one red.v4 per (distinct cell, quad).
// ---------------------------------------------------------------------------
__global__ __launch_bounds__(256) void lss_main(const float* __restrict__ ctx,
                                                const float* __restrict__ dl) {
    int blk = blockIdx.x;               // bn*FW_ + w
    int bn  = blk / FW_;
    int w   = blk - bn * FW_;
    int b   = bn / N_;
    int tid = threadIdx.x;
    int lane = tid & 31, wrp = tid >> 5;

    __shared__ int   skey[CAP_];
    __shared__ float swsum[CAP_ * FH_];     // [slot][pixel]
    __shared__ float sctx[FH_][C_];         // [pixel][channel]
    __shared__ int   slist[CAP_];
    __shared__ int   s_n;

    for (int i = tid; i < CAP_; i += 256) skey[i] = -1;
    for (int i = tid; i < CAP_ * FH_; i += 256) swsum[i] = 0.f;
    if (tid == 0) s_n = 0;

    for (int i = tid; i < FH_ * C_; i += 256) {
        int p = i / C_, c = i - p * C_;
        sctx[p][c] = ctx[(bn * C_ + c) * PIX_ + p * FW_ + w];
    }
    __syncthreads();

    bool act = (lane < D_ / 4);             // 28 active lanes

    for (int p = wrp; p < FH_; p += 8) {
        int hw = p * FW_ + w;
        const float* dlp = dl + (size_t)(bn * D_) * PIX_ + hw;

        // softmax: lane owns depths 4*lane .. 4*lane+3
        float l[4];
        #pragma unroll
        for (int r = 0; r < 4; r++)
            l[r] = act ? dlp[(size_t)(4 * lane + r) * PIX_] : -1e30f;
        float m = fmaxf(fmaxf(l[0], l[1]), fmaxf(l[2], l[3]));
        #pragma unroll
        for (int s = 16; s > 0; s >>= 1) m = fmaxf(m, __shfl_xor_sync(0xffffffffu, m, s));
        float e[4];
        float sum = 0.f;
        #pragma unroll
        for (int r = 0; r < 4; r++) {
            e[r] = act ? __expf(l[r] - m) : 0.f;
            sum += e[r];
        }
        #pragma unroll
        for (int s = 16; s > 0; s >>= 1) sum += __shfl_xor_sync(0xffffffffu, sum, s);
        float rinv = 1.0f / sum;

        // per-pixel quadratic geometry coefficients
        float u = (703.0f / 43.0f) * (float)w;
        float v = (float)(17 * p);
        const float* Ii = g_idainv[bn];
        float a0 = Ii[0]*u  + Ii[1]*v  + Ii[3];
        float a1 = Ii[4]*u  + Ii[5]*v  + Ii[7];
        float a2 = Ii[8]*u  + Ii[9]*v  + Ii[11];
        float a3 = Ii[12]*u + Ii[13]*v + Ii[15];
        float b0 = Ii[2], b1 = Ii[6], b2 = Ii[10], b3 = Ii[14];
        const float* Cm = g_comb[bn];
        float Ax[3], Bx[3], Cx[3];
        const float LO[3] = { -50.8f - 0.4f, -50.8f - 0.4f, -1.0f - 4.0f };
        #pragma unroll
        for (int ax = 0; ax < 3; ax++) {
            const float* Cr = Cm + ax * 4;
            Ax[ax] = Cr[0]*(a0*a2) + Cr[1]*(a1*a2) + Cr[2]*a2 + Cr[3]*a3 - LO[ax];
            Bx[ax] = Cr[0]*(a0*b2 + b0*a2) + Cr[1]*(a1*b2 + b1*a2) + Cr[2]*b2 + Cr[3]*b3;
            Cx[ax] = Cr[0]*(b0*b2) + Cr[1]*(b1*b2);
        }

        // in-register run merge over this lane's 4 consecutive depths
        int   curcell = -1;
        float curw = 0.f;
        if (act) {
            #pragma unroll
            for (int r = 0; r < 4; r++) {
                int di = 4 * lane + r;
                float wgt = e[r] * rinv;
                float dd = 2.25f + 0.5f * (float)di;
                const float INV08 = 1.0f / 0.8f;
                float gx = fmaf(dd, fmaf(dd, Cx[0], Bx[0]), Ax[0]);
                float gy = fmaf(dd, fmaf(dd, Cx[1], Bx[1]), Ax[1]);
                float gz = fmaf(dd, fmaf(dd, Cx[2], Bx[2]), Ax[2]);
                int ix = __float2int_rd(gx * INV08);
                int iy = __float2int_rd(gy * INV08);
                int iz = __float2int_rd(gz * 0.125f);
                int cell = -1;
                if (((unsigned)ix < (unsigned)NX_) && ((unsigned)iy < (unsigned)NY_) && (iz == 0))
                    cell = iy * NX_ + ix;
                if (cell == curcell) {
                    curw += wgt;
                } else {
                    // flush previous segment
                    if (curcell >= 0) {
                        unsigned hsh = ((unsigned)curcell * 2654435761u) >> 7;
                        int slot = -1;
                        for (int probe = 0; probe < CAP_; probe++) {
                            int sidx = (int)((hsh + probe) & (CAP_ - 1));
                            int k = skey[sidx];
                            if (k == curcell) { slot = sidx; break; }
                            if (k == -1) {
                                int old = atomicCAS(&skey[sidx], -1, curcell);
                                if (old == -1) {
                                    int li = atomicAdd(&s_n, 1);
                                    slist[li] = sidx;
                                    slot = sidx; break;
                                }
                                if (old == curcell) { slot = sidx; break; }
                            }
                        }
                        atomicAdd(&swsum[slot * FH_ + p], curw);
                    }
                    curcell = cell;
                    curw = wgt;
                }
            }
            // flush tail segment
            if (curcell >= 0) {
                unsigned hsh = ((unsigned)curcell * 2654435761u) >> 7;
                int slot = -1;
                for (int probe = 0; probe < CAP_; probe++) {
                    int sidx = (int)((hsh + probe) & (CAP_ - 1));
                    int k = skey[sidx];
                    if (k == curcell) { slot = sidx; break; }
                    if (k == -1) {
                        int old = atomicCAS(&skey[sidx], -1, curcell);
                        if (old == -1) {
                            int li = atomicAdd(&s_n, 1);
                            slist[li] = sidx;
                            slot = sidx; break;
                        }
                        if (old == curcell) { slot = sidx; break; }
                    }
                }
                atomicAdd(&swsum[slot * FH_ + p], curw);
            }
        }
    }
    __syncthreads();

    // ---- phase 3: one red.v4 per (distinct cell, channel quad) ----
    int n = s_n;
    int total = n * NQ_;
    float4* sc4 = (float4*)g_scratch;
    for (int t = tid; t < total; t += 256) {
        int eidx = t / NQ_;
        int q    = t - eidx * NQ_;
        int slot = slist[eidx];
        int cell = skey[slot];
        const float4* wp4 = (const float4*)&swsum[slot * FH_];
        float acc0 = 0.f, acc1 = 0.f, acc2 = 0.f, acc3 = 0.f;
        #pragma unroll
        for (int pv = 0; pv < 4; pv++) {
            float4 wv = wp4[pv];
            float wvv[4] = { wv.x, wv.y, wv.z, wv.w };
            #pragma unroll
            for (int j = 0; j < 4; j++) {
                int p = pv * 4 + j;
                float wgt = wvv[j];
                acc0 = fmaf(wgt, sctx[p][q*4+0], acc0);
                acc1 = fmaf(wgt, sctx[p][q*4+1], acc1);
                acc2 = fmaf(wgt, sctx[p][q*4+2], acc2);
                acc3 = fmaf(wgt, sctx[p][q*4+3], acc3);
            }
        }
        float* addr = (float*)(sc4 + ((size_t)(b * NQ_ + q) * CELLS_ + cell));
        asm volatile("red.global.add.v4.f32 [%0], {%1, %2, %3, %4};"
                     :: "l"(addr), "f"(acc0), "f"(acc1), "f"(acc2), "f"(acc3)
                     : "memory");
    }
}

// ---------------------------------------------------------------------------
// transpose: quad-planar scratch [B][NQ][CELLS][4] -> out [B][C][CELLS]
//   fully coalesced: LDG.128 in, STG.128 out, 4x256 smem tile per CTA.
//   grid = B * NQ * (CELLS/256) = 2560 CTAs of 256 threads.
// ---------------------------------------------------------------------------
__global__ __launch_bounds__(256) void transpose_kernel(float* __restrict__ out) {
    __shared__ float tile[4][256];
    int id    = blockIdx.x;
    int chunk = id & (CELLS_ / 256 - 1);        // 64 chunks
    int q     = (id >> 6) % NQ_;
    int b     = id / (64 * NQ_);
    int cell0 = chunk * 256;
    int tid   = threadIdx.x;

    const float4* src = (const float4*)g_scratch + ((size_t)(b * NQ_ + q) * CELLS_ + cell0);
    float4 v = src[tid];
    tile[0][tid] = v.x; tile[1][tid] = v.y; tile[2][tid] = v.z; tile[3][tid] = v.w;
    __syncthreads();

    int j  = tid >> 6;            // channel within quad (0..3)
    int c4 = (tid & 63) << 2;     // cell group of 4
    float4 o = *(const float4*)&tile[j][c4];
    *(float4*)(out + ((size_t)(b * C_ + q * 4 + j)) * CELLS_ + cell0 + c4) = o;
}

// ---------------------------------------------------------------------------
extern "C" void kernel_launch(void* const* d_in, const int* in_sizes, int n_in,
                              void* d_out, int out_size) {
    const float* ctx    = (const float*)d_in[0];
    const float* dl     = (const float*)d_in[1];
    const float* s2e    = (const float*)d_in[2];
    const float* intrin = (const float*)d_in[3];
    const float* ida    = (const float*)d_in[4];
    const float* bda    = (const float*)d_in[5];
    float* out = (float*)d_out;

    zero_scratch_kernel<<<OUTN_ / 16 / 256, 256>>>();
    prep_kernel<<<1, 384>>>(s2e, intrin, ida, bda);
    lss_main<<<BN_ * FW_, 256>>>(ctx, dl);
    transpose_kernel<<<B_ * NQ_ * (CELLS_ / 256), 256>>>(out);
}

// round 16
// speedup vs baseline: 1.2721x; 1.2721x over previous
#include <cuda_runtime.h>
#include <math.h>

#define B_   2
#define N_   6
#define C_   80
#define FH_  16
#define FW_  44
#define D_   112
#define NX_  128
#define NY_  128
#define BN_  (B_*N_)
#define PIX_ (FH_*FW_)          // 704
#define NPIX_ (BN_*PIX_)        // 8448
#define CELLS_ (NX_*NY_)        // 16384
#define NQ_  (C_/4)             // 20 channel quads
#define OUTN_ (B_*C_*CELLS_)    // 2621440
#define CAP_  256               // smem hash capacity (distinct cells/column ~70)

__device__ float g_comb[BN_][16];    // bda @ s2e @ inv(intrin)
__device__ float g_idainv[BN_][16];  // inv(ida)
// quad-planar accumulator: float4 plane per (b, q): [B][NQ][CELLS][4]
__device__ __align__(128) float g_scratch[OUTN_];

// ---------------------------------------------------------------------------
// parallel prep: one block, 384 threads (entry-parallel adjugate inverses)
// ---------------------------------------------------------------------------
__global__ __launch_bounds__(384) void prep_kernel(const float* __restrict__ s2e,
                                                   const float* __restrict__ intrin,
                                                   const float* __restrict__ ida,
                                                   const float* __restrict__ bda) {
    __shared__ double adj[2][BN_][16];
    __shared__ double rdet[2][BN_];
    __shared__ double Tm[BN_][16];
    int t = threadIdx.x;

    if (t < 2 * BN_ * 16) {
        int pair = t / (BN_ * 16);
        int rem  = t - pair * (BN_ * 16);
        int i    = rem >> 4;
        int k    = rem & 15;
        const float* src = (pair ? ida : intrin) + i * 16;
        double m[16];
        #pragma unroll
        for (int j = 0; j < 16; j++) m[j] = (double)src[j];
        int r = k >> 2, c = k & 3;
        int rr[3], cc[3], nr = 0, nc = 0;
        #pragma unroll
        for (int j = 0; j < 4; j++) { if (j != c) rr[nr++] = j; }
        #pragma unroll
        for (int j = 0; j < 4; j++) { if (j != r) cc[nc++] = j; }
        double a = m[rr[0]*4+cc[0]], bb = m[rr[0]*4+cc[1]], cx = m[rr[0]*4+cc[2]];
        double d = m[rr[1]*4+cc[0]], e  = m[rr[1]*4+cc[1]], f  = m[rr[1]*4+cc[2]];
        double g = m[rr[2]*4+cc[0]], h  = m[rr[2]*4+cc[1]], ii = m[rr[2]*4+cc[2]];
        double det3 = a*(e*ii - f*h) - bb*(d*ii - f*g) + cx*(d*h - e*g);
        adj[pair][i][k] = (((r + c) & 1) ? -det3 : det3);
    }
    __syncthreads();

    if (t < 2 * BN_) {
        int pair = t / BN_;
        int i    = t - pair * BN_;
        const float* src = (pair ? ida : intrin) + i * 16;
        double det = 0.0;
        #pragma unroll
        for (int j = 0; j < 4; j++) det += (double)src[j] * adj[pair][i][j*4];
        rdet[pair][i] = 1.0 / det;
    }
    __syncthreads();

    if (t < 2 * BN_ * 16) {
        int pair = t / (BN_ * 16);
        int rem  = t - pair * (BN_ * 16);
        adj[pair][rem >> 4][rem & 15] *= rdet[pair][rem >> 4];
    }
    __syncthreads();

    if (t < BN_ * 16) {
        int i = t >> 4, k = t & 15;
        int r = k >> 2, c = k & 3;
        double s = 0.0;
        #pragma unroll
        for (int j = 0; j < 4; j++) s += (double)s2e[i*16 + r*4 + j] * adj[0][i][j*4 + c];
        Tm[i][k] = s;
    }
    __syncthreads();

    if (t < BN_ * 16) {
        int i = t >> 4, k = t & 15;
        int r = k >> 2, c = k & 3;
        int b = i / N_;
        double s = 0.0;
        #pragma unroll
        for (int j = 0; j < 4; j++) s += (double)bda[b*16 + r*4 + j] * Tm[i][j*4 + c];
        g_comb[i][k]   = (float)s;
        g_idainv[i][k] = (float)adj[1][i][k];
    }
}

__global__ __launch_bounds__(256) void zero_scratch_kernel() {
    int i = blockIdx.x * blockDim.x + threadIdx.x;
    float4* p = (float4*)g_scratch + i * 4;
    #pragma unroll
    for (int j = 0; j < 4; j++) p[j] = make_float4(0.f, 0.f, 0.f, 0.f);
}

// ---------------------------------------------------------------------------
// column-fused main (R14 structure): one CTA (256 thr, 8 warps) per (bn, w).
//   Each warp: 2 pixels. Register softmax (lane owns depths lane+32r) ->
//   quadratic geometry -> smem hash accumulate -> one red.v4 per
//   (distinct cell, quad) into quad-planar scratch.
// ---------------------------------------------------------------------------
__global__ __launch_bounds__(256) void lss_main(const float* __restrict__ ctx,
                                                const float* __restrict__ dl) {
    int blk = blockIdx.x;               // bn*FW_ + w
    int bn  = blk / FW_;
    int w   = blk - bn * FW_;
    int b   = bn / N_;
    int tid = threadIdx.x;
    int lane = tid & 31, wrp = tid >> 5;

    __shared__ int   skey[CAP_];
    __shared__ float swsum[CAP_ * FH_];     // [slot][pixel]
    __shared__ float sctx[FH_][C_];         // [pixel][channel]
    __shared__ int   slist[CAP_];
    __shared__ int   s_n;

    for (int i = tid; i < CAP_; i += 256) skey[i] = -1;
    for (int i = tid; i < CAP_ * FH_; i += 256) swsum[i] = 0.f;
    if (tid == 0) s_n = 0;

    for (int i = tid; i < FH_ * C_; i += 256) {
        int p = i / C_, c = i - p * C_;
        sctx[p][c] = ctx[(bn * C_ + c) * PIX_ + p * FW_ + w];
    }
    __syncthreads();

    // ---- per-warp: 2 pixels each ----
    for (int p = wrp; p < FH_; p += 8) {
        int hw = p * FW_ + w;
        const float* dlp = dl + (size_t)(bn * D_) * PIX_ + hw;

        // register softmax over D=112 (4 depths per lane, strided by 32)
        float l0 = dlp[(size_t)lane * PIX_];
        float l1 = dlp[(size_t)(lane + 32) * PIX_];
        float l2 = dlp[(size_t)(lane + 64) * PIX_];
        float l3 = (lane < 16) ? dlp[(size_t)(lane + 96) * PIX_] : -1e30f;
        float m = fmaxf(fmaxf(l0, l1), fmaxf(l2, l3));
        #pragma unroll
        for (int s = 16; s > 0; s >>= 1) m = fmaxf(m, __shfl_xor_sync(0xffffffffu, m, s));
        float e0 = __expf(l0 - m), e1 = __expf(l1 - m), e2 = __expf(l2 - m);
        float e3 = (lane < 16) ? __expf(l3 - m) : 0.f;
        float sum = e0 + e1 + e2 + e3;
        #pragma unroll
        for (int s = 16; s > 0; s >>= 1) sum += __shfl_xor_sync(0xffffffffu, sum, s);
        float rinv = 1.0f / sum;

        // per-pixel quadratic geometry coefficients (lane-redundant, cheap)
        float u = (703.0f / 43.0f) * (float)w;   // linspace(0,703,44)
        float v = (float)(17 * p);               // linspace(0,255,16), exact
        const float* Ii = g_idainv[bn];
        float a0 = Ii[0]*u  + Ii[1]*v  + Ii[3];
        float a1 = Ii[4]*u  + Ii[5]*v  + Ii[7];
        float a2 = Ii[8]*u  + Ii[9]*v  + Ii[11];
        float a3 = Ii[12]*u + Ii[13]*v + Ii[15];
        float b0 = Ii[2], b1 = Ii[6], b2 = Ii[10], b3 = Ii[14];
        const float* Cm = g_comb[bn];
        float Ax[3], Bx[3], Cx[3];
        const float LO[3] = { -50.8f - 0.4f, -50.8f - 0.4f, -1.0f - 4.0f };
        #pragma unroll
        for (int ax = 0; ax < 3; ax++) {
            const float* Cr = Cm + ax * 4;
            Ax[ax] = Cr[0]*(a0*a2) + Cr[1]*(a1*a2) + Cr[2]*a2 + Cr[3]*a3 - LO[ax];
            Bx[ax] = Cr[0]*(a0*b2 + b0*a2) + Cr[1]*(a1*b2 + b1*a2) + Cr[2]*b2 + Cr[3]*b3;
            Cx[ax] = Cr[0]*(b0*b2) + Cr[1]*(b1*b2);
        }

        float ee[4] = { e0, e1, e2, e3 };
        #pragma unroll
        for (int r = 0; r < 4; r++) {
            int di = lane + 32 * r;
            if (r == 3 && lane >= 16) continue;
            float wgt = ee[r] * rinv;
            float dd = 2.25f + 0.5f * (float)di;       // exact
            const float INV08 = 1.0f / 0.8f;
            float gx = fmaf(dd, fmaf(dd, Cx[0], Bx[0]), Ax[0]);
            float gy = fmaf(dd, fmaf(dd, Cx[1], Bx[1]), Ax[1]);
            float gz = fmaf(dd, fmaf(dd, Cx[2], Bx[2]), Ax[2]);
            int ix = __float2int_rd(gx * INV08);
            int iy = __float2int_rd(gy * INV08);
            int iz = __float2int_rd(gz * 0.125f);      // /8.0 bit-exact
            if (((unsigned)ix < (unsigned)NX_) && ((unsigned)iy < (unsigned)NY_) && (iz == 0)) {
                int cell = iy * NX_ + ix;
                // hash insert / find
                unsigned hsh = ((unsigned)cell * 2654435761u) >> 7;
                int slot = -1;
                for (int probe = 0; probe < CAP_; probe++) {
                    int sidx = (int)((hsh + probe) & (CAP_ - 1));
                    int k = skey[sidx];
                    if (k == cell) { slot = sidx; break; }
                    if (k == -1) {
                        int old = atomicCAS(&skey[sidx], -1, cell);
                        if (old == -1) {
                            int li = atomicAdd(&s_n, 1);
                            slist[li] = sidx;
                            slot = sidx; break;
                        }
                        if (old == cell) { slot = sidx; break; }
                    }
                }
                atomicAdd(&swsum[slot * FH_ + p], wgt);
            }
        }
    }
    __syncthreads();

    // ---- phase 3: one red.v4 per (distinct cell, channel quad) into
    //      quad-planar scratch [B][NQ][CELLS][4] ----
    int n = s_n;
    int total = n * NQ_;
    float4* sc4 = (float4*)g_scratch;
    for (int t = tid; t < total; t += 256) {
        int eidx = t / NQ_;
        int q    = t - eidx * NQ_;
        int slot = slist[eidx];
        int cell = skey[slot];
        const float4* wp4 = (const float4*)&swsum[slot * FH_];
        float acc0 = 0.f, acc1 = 0.f, acc2 = 0.f, acc3 = 0.f;
        #pragma unroll
        for (int pv = 0; pv < 4; pv++) {
            float4 wv = wp4[pv];
            float wvv[4] = { wv.x, wv.y, wv.z, wv.w };
            #pragma unroll
            for (int j = 0; j < 4; j++) {
                int p = pv * 4 + j;
                float wgt = wvv[j];
                acc0 = fmaf(wgt, sctx[p][q*4+0], acc0);
                acc1 = fmaf(wgt, sctx[p][q*4+1], acc1);
                acc2 = fmaf(wgt, sctx[p][q*4+2], acc2);
                acc3 = fmaf(wgt, sctx[p][q*4+3], acc3);
            }
        }
        float* addr = (float*)(sc4 + ((size_t)(b * NQ_ + q) * CELLS_ + cell));
        asm volatile("red.global.add.v4.f32 [%0], {%1, %2, %3, %4};"
                     :: "l"(addr), "f"(acc0), "f"(acc1), "f"(acc2), "f"(acc3)
                     : "memory");
    }
}

// ---------------------------------------------------------------------------
// transpose: quad-planar scratch [B][NQ][CELLS][4] -> out [B][C][CELLS]
//   fully coalesced: LDG.128 in, STG.128 out, 4x256 smem tile per CTA.
// ---------------------------------------------------------------------------
__global__ __launch_bounds__(256) void transpose_kernel(float* __restrict__ out) {
    __shared__ float tile[4][256];
    int id    = blockIdx.x;
    int chunk = id & (CELLS_ / 256 - 1);        // 64 chunks
    int q     = (id >> 6) % NQ_;
    int b     = id / (64 * NQ_);
    int cell0 = chunk * 256;
    int tid   = threadIdx.x;

    const float4* src = (const float4*)g_scratch + ((size_t)(b * NQ_ + q) * CELLS_ + cell0);
    float4 v = src[tid];
    tile[0][tid] = v.x; tile[1][tid] = v.y; tile[2][tid] = v.z; tile[3][tid] = v.w;
    __syncthreads();

    int j  = tid >> 6;            // channel within quad (0..3)
    int c4 = (tid & 63) << 2;     // cell group of 4
    float4 o = *(const float4*)&tile[j][c4];
    *(float4*)(out + ((size_t)(b * C_ + q * 4 + j)) * CELLS_ + cell0 + c4) = o;
}

// ---------------------------------------------------------------------------
extern "C" void kernel_launch(void* const* d_in, const int* in_sizes, int n_in,
                              void* d_out, int out_size) {
    const float* ctx    = (const float*)d_in[0];
    const float* dl     = (const float*)d_in[1];
    const float* s2e    = (const float*)d_in[2];
    const float* intrin = (const float*)d_in[3];
    const float* ida    = (const float*)d_in[4];
    const float* bda    = (const float*)d_in[5];
    float* out = (float*)d_out;

    zero_scratch_kernel<<<OUTN_ / 16 / 256, 256>>>();
    prep_kernel<<<1, 384>>>(s2e, intrin, ida, bda);
    lss_main<<<BN_ * FW_, 256>>>(ctx, dl);
    transpose_kernel<<<B_ * NQ_ * (CELLS_ / 256), 256>>>(out);
}